// round 14
// baseline (speedup 1.0000x reference)
#include <cuda_runtime.h>

#define Bc 4
#define Cc 64
#define Ec 8
#define Nn 4096
#define Ti 256
#define L2E 1.4426950408889634f

typedef unsigned long long ull;

// ---- static scratch (no allocations allowed) ----
// f/h stored pair-replicated: d_f2[b][e2][i] = { (f[2e2,i],f[2e2,i]), (f[2e2+1,i],f[2e2+1,i]) }
__device__ __align__(16) ulonglong2 d_f2[Bc * 4 * Nn];
__device__ __align__(16) ulonglong2 d_h2[Bc * 4 * Nn];
__device__ __align__(16) float d_g[Bc * Ec * Nn];

// ---- packed f32x2 helpers (Blackwell) ----
__device__ __forceinline__ ull pk2(float a, float b) {
    ull r; asm("mov.b64 %0,{%1,%2};" : "=l"(r) : "f"(a), "f"(b)); return r;
}
__device__ __forceinline__ float2 up2(ull v) {
    float2 r; asm("mov.b64 {%0,%1},%2;" : "=f"(r.x), "=f"(r.y) : "l"(v)); return r;
}
__device__ __forceinline__ ull fma2(ull a, ull b, ull c) {
    ull d; asm("fma.rn.f32x2 %0,%1,%2,%3;" : "=l"(d) : "l"(a), "l"(b), "l"(c)); return d;
}
__device__ __forceinline__ float ex2(float x) {
    float r; asm("ex2.approx.f32 %0,%1;" : "=f"(r) : "f"(x)); return r;
}

// ============================================================
// Kernel A: projections. 128 CTAs x 128 threads.
// Writes g plain, f/h pair-replicated ulonglong2.
// ============================================================
__global__ __launch_bounds__(128) void proj_kernel(
    const float* __restrict__ x,
    const float* __restrict__ Wk, const float* __restrict__ bk,
    const float* __restrict__ Wq, const float* __restrict__ bq,
    const float* __restrict__ Wv, const float* __restrict__ bv)
{
    __shared__ float Wks[Ec * Cc], Wqs[Ec * Cc], Wvs[Ec * Cc];
    __shared__ float bks[Ec], bqs[Ec], bvs[Ec];
    const int t = threadIdx.x;
    const int b = blockIdx.y;
    const int n = blockIdx.x * 128 + t;
    for (int i = t; i < Ec * Cc; i += 128) { Wks[i] = Wk[i]; Wqs[i] = Wq[i]; Wvs[i] = Wv[i]; }
    if (t < Ec) { bks[t] = bk[t]; bqs[t] = bq[t]; bvs[t] = bv[t]; }
    __syncthreads();

    float xc[Cc];
    const float* xb = x + (size_t)b * Cc * Nn + n;
#pragma unroll
    for (int c = 0; c < Cc; c++) xc[c] = xb[(size_t)c * Nn];

    float fv[Ec], gv[Ec], hv[Ec];
#pragma unroll
    for (int e = 0; e < Ec; e++) {
        float af = bks[e], ag = bqs[e], av = bvs[e];
#pragma unroll
        for (int c = 0; c < Cc; c++) {
            float xv = xc[c];
            af = fmaf(Wks[e * Cc + c], xv, af);
            ag = fmaf(Wqs[e * Cc + c], xv, ag);
            av = fmaf(Wvs[e * Cc + c], xv, av);
        }
        fv[e] = af; gv[e] = ag; hv[e] = av;
    }
#pragma unroll
    for (int e = 0; e < Ec; e++) d_g[(b * Ec + e) * Nn + n] = gv[e];
#pragma unroll
    for (int e2 = 0; e2 < 4; e2++) {
        ulonglong2 rf, rh;
        rf.x = pk2(fv[2 * e2], fv[2 * e2]);     rf.y = pk2(fv[2 * e2 + 1], fv[2 * e2 + 1]);
        rh.x = pk2(hv[2 * e2], hv[2 * e2]);     rh.y = pk2(hv[2 * e2 + 1], hv[2 * e2 + 1]);
        d_f2[(b * 4 + e2) * Nn + n] = rf;
        d_h2[(b * 4 + e2) * Nn + n] = rh;
    }
}

// ============================================================
// Kernel B: attention + fused output projection.
// CTA = (batch, 64-column block), 256 threads, 8 warps, 2 CTAs/SM.
// Each lane owns 2 consecutive columns (one f32x2 pair); warp spans
// all 64 columns; the 8 warps split the i-range.
//   pass1: l[j] = sum_i exp(f_i . g_j)        -> lr[j] = -log2 l[j]
//   pass2: beta[i,j] = ex2(s*log2e + lr[j])   (STG.64 per lane)
//          v[e,j] += h[e,i] * beta
//   epilogue: y = leaky(gamma*(Wo v + bo) + x)
// ============================================================
struct __align__(16) Sm {
    union {
        struct { ulonglong2 fs[4][Ti]; ulonglong2 hs[4][Ti]; } t;  // 32 KB
        float vsc[8][Ec][64];                                      // 16 KB (reduction)
    } u;
    float lred[8][64];    // warp partials for l; reused as final v[e][j]
    float lr[64];         // -log2(l[j])
    float Wos[Cc * Ec];
    float bos[Cc];
};

__global__ __launch_bounds__(256, 2) void attn_kernel(
    const float* __restrict__ x,
    const float* __restrict__ Wo, const float* __restrict__ bo,
    const float* __restrict__ gamma,
    float* __restrict__ out_y, float* __restrict__ out_beta)
{
    __shared__ Sm sm;

    const int tid  = threadIdx.x;
    const int lane = tid & 31;
    const int wp   = tid >> 5;
    const int b    = blockIdx.y;
    const int jbase = blockIdx.x * 64;
    const int j0   = jbase + lane * 2;

    // preload output-proj weights (used only in epilogue)
    for (int i = tid; i < Cc * Ec; i += 256) sm.Wos[i] = Wo[i];
    if (tid < Cc) sm.bos[tid] = bo[tid];

    // g for this lane's 2 columns, packed (j0, j0+1)
    ull gP[Ec];
    const float* gb = d_g + b * Ec * Nn;
#pragma unroll
    for (int e = 0; e < Ec; e++) {
        float2 g2 = *(const float2*)(gb + e * Nn + j0);
        gP[e] = pk2(g2.x, g2.y);
    }

    const ulonglong2* fb = d_f2 + b * 4 * Nn;
    const ulonglong2* hb = d_h2 + b * 4 * Nn;

    // ---------------- pass 1: column sums ----------------
    float ls0 = 0.f, ls1 = 0.f;
    for (int t0 = 0; t0 < Nn; t0 += Ti) {
        __syncthreads();
#pragma unroll
        for (int e2 = 0; e2 < 4; e2++)
            sm.u.t.fs[e2][tid] = fb[e2 * Nn + t0 + tid];
        __syncthreads();
#pragma unroll
        for (int k = 0; k < 8; k++) {
            const int ib = k * 32 + wp * 4;
#pragma unroll
            for (int c = 0; c < 4; c++) {
                const int i = ib + c;
                ull s01 = 0ULL;
#pragma unroll
                for (int e2 = 0; e2 < 4; e2++) {
                    ulonglong2 fv = sm.u.t.fs[e2][i];
                    s01 = fma2(fv.x, gP[2 * e2], s01);
                    s01 = fma2(fv.y, gP[2 * e2 + 1], s01);
                }
                float2 a = up2(s01);
                ls0 += ex2(a.x * L2E);
                ls1 += ex2(a.y * L2E);
            }
        }
    }
    __syncthreads();
    *(float2*)&sm.lred[wp][lane * 2] = make_float2(ls0, ls1);
    __syncthreads();
    if (tid < 64) {
        float s = 0.f;
#pragma unroll
        for (int w = 0; w < 8; w++) s += sm.lred[w][tid];
        sm.lr[tid] = -__log2f(s);
    }
    __syncthreads();
    const float lr0 = sm.lr[lane * 2 + 0];
    const float lr1 = sm.lr[lane * 2 + 1];

    // ---------------- pass 2: beta + v ----------------
    ull vP[Ec];
#pragma unroll
    for (int e = 0; e < Ec; e++) vP[e] = 0ULL;
    float* bout = out_beta + (size_t)b * Nn * Nn + j0;

    for (int t0 = 0; t0 < Nn; t0 += Ti) {
        __syncthreads();
#pragma unroll
        for (int e2 = 0; e2 < 4; e2++) {
            sm.u.t.fs[e2][tid] = fb[e2 * Nn + t0 + tid];
            sm.u.t.hs[e2][tid] = hb[e2 * Nn + t0 + tid];
        }
        __syncthreads();
#pragma unroll
        for (int k = 0; k < 8; k++) {
            const int ib = k * 32 + wp * 4;
#pragma unroll
            for (int c = 0; c < 4; c++) {
                const int i = ib + c;
                ull s01 = 0ULL;
#pragma unroll
                for (int e2 = 0; e2 < 4; e2++) {
                    ulonglong2 fv = sm.u.t.fs[e2][i];
                    s01 = fma2(fv.x, gP[2 * e2], s01);
                    s01 = fma2(fv.y, gP[2 * e2 + 1], s01);
                }
                float2 a = up2(s01);
                float b0 = ex2(fmaf(a.x, L2E, lr0));
                float b1 = ex2(fmaf(a.y, L2E, lr1));
                *(float2*)(bout + (size_t)(t0 + i) * Nn) = make_float2(b0, b1);
                ull b01 = pk2(b0, b1);
#pragma unroll
                for (int e2 = 0; e2 < 4; e2++) {
                    ulonglong2 hv = sm.u.t.hs[e2][i];
                    vP[2 * e2]     = fma2(hv.x, b01, vP[2 * e2]);
                    vP[2 * e2 + 1] = fma2(hv.y, b01, vP[2 * e2 + 1]);
                }
            }
        }
    }

    // ---------------- reduce v across warps ----------------
    __syncthreads();   // tiles no longer needed; vsc overlays them
#pragma unroll
    for (int e = 0; e < Ec; e++) {
        float2 a = up2(vP[e]);
        *(float2*)&sm.u.vsc[wp][e][lane * 2] = a;
    }
    __syncthreads();
    for (int m = tid; m < Ec * 64; m += 256) {
        const int e = m >> 6, jl = m & 63;
        float s = 0.f;
#pragma unroll
        for (int w = 0; w < 8; w++) s += sm.u.vsc[w][e][jl];
        sm.lred[e][jl] = s;   // final v[e][jl]
    }
    __syncthreads();

    // ---------------- fused output projection ----------------
    const float gm = *gamma;
    const int jl = tid & 63;
    const int ch = (tid >> 6) * 16;           // 4 groups x 16 channels
    const float* xb = x + (size_t)b * Cc * Nn + jbase + jl;
    float* yb = out_y + (size_t)b * Cc * Nn + jbase + jl;
    float ve[Ec];
#pragma unroll
    for (int e = 0; e < Ec; e++) ve[e] = sm.lred[e][jl];
#pragma unroll
    for (int cc = 0; cc < 16; cc++) {
        const int c = ch + cc;
        float o = sm.bos[c];
#pragma unroll
        for (int e = 0; e < Ec; e++) o = fmaf(sm.Wos[c * Ec + e], ve[e], o);
        float y = fmaf(gm, o, xb[(size_t)c * Nn]);
        yb[(size_t)c * Nn] = (y >= 0.f) ? y : 0.01f * y;
    }
}

extern "C" void kernel_launch(void* const* d_in, const int* in_sizes, int n_in,
                              void* d_out, int out_size)
{
    const float* x     = (const float*)d_in[0];
    const float* Wk    = (const float*)d_in[1];
    const float* bk    = (const float*)d_in[2];
    const float* Wq    = (const float*)d_in[3];
    const float* bq    = (const float*)d_in[4];
    const float* Wv    = (const float*)d_in[5];
    const float* bv    = (const float*)d_in[6];
    const float* Wo    = (const float*)d_in[7];
    const float* bo    = (const float*)d_in[8];
    const float* gamma = (const float*)d_in[9];

    float* out_y    = (float*)d_out;                 // [B,C,H,W] first
    float* out_beta = out_y + (size_t)Bc * Cc * Nn;  // then [B,N,N]

    proj_kernel<<<dim3(Nn / 128, Bc), 128>>>(x, Wk, bk, Wq, bq, Wv, bv);
    attn_kernel<<<dim3(Nn / 64, Bc), 256>>>(x, Wo, bo, gamma, out_y, out_beta);
}

// round 15
// speedup vs baseline: 1.0023x; 1.0023x over previous
#include <cuda_runtime.h>

#define Bc 4
#define Cc 64
#define Ec 8
#define Nn 4096
#define Ti 256
#define L2E 1.4426950408889634f

typedef unsigned long long ull;

// ---- static scratch (no allocations allowed) ----
// f/h stored pair-replicated: d_f2[b][e2][i] = { (f[2e2,i],f[2e2,i]), (f[2e2+1,i],f[2e2+1,i]) }
__device__ __align__(16) ulonglong2 d_f2[Bc * 4 * Nn];
__device__ __align__(16) ulonglong2 d_h2[Bc * 4 * Nn];
__device__ __align__(16) float d_g[Bc * Ec * Nn];

// ---- packed f32x2 helpers (Blackwell) ----
__device__ __forceinline__ ull pk2(float a, float b) {
    ull r; asm("mov.b64 %0,{%1,%2};" : "=l"(r) : "f"(a), "f"(b)); return r;
}
__device__ __forceinline__ float2 up2(ull v) {
    float2 r; asm("mov.b64 {%0,%1},%2;" : "=f"(r.x), "=f"(r.y) : "l"(v)); return r;
}
__device__ __forceinline__ ull fma2(ull a, ull b, ull c) {
    ull d; asm("fma.rn.f32x2 %0,%1,%2,%3;" : "=l"(d) : "l"(a), "l"(b), "l"(c)); return d;
}
__device__ __forceinline__ float ex2(float x) {
    float r; asm("ex2.approx.f32 %0,%1;" : "=f"(r) : "f"(x)); return r;
}

// ============================================================
// Kernel A: projections. 128 CTAs x 128 threads.
// Writes g plain, f/h pair-replicated ulonglong2.
// ============================================================
__global__ __launch_bounds__(128) void proj_kernel(
    const float* __restrict__ x,
    const float* __restrict__ Wk, const float* __restrict__ bk,
    const float* __restrict__ Wq, const float* __restrict__ bq,
    const float* __restrict__ Wv, const float* __restrict__ bv)
{
    __shared__ float Wks[Ec * Cc], Wqs[Ec * Cc], Wvs[Ec * Cc];
    __shared__ float bks[Ec], bqs[Ec], bvs[Ec];
    const int t = threadIdx.x;
    const int b = blockIdx.y;
    const int n = blockIdx.x * 128 + t;
    for (int i = t; i < Ec * Cc; i += 128) { Wks[i] = Wk[i]; Wqs[i] = Wq[i]; Wvs[i] = Wv[i]; }
    if (t < Ec) { bks[t] = bk[t]; bqs[t] = bq[t]; bvs[t] = bv[t]; }
    __syncthreads();

    float xc[Cc];
    const float* xb = x + (size_t)b * Cc * Nn + n;
#pragma unroll
    for (int c = 0; c < Cc; c++) xc[c] = xb[(size_t)c * Nn];

    float fv[Ec], gv[Ec], hv[Ec];
#pragma unroll
    for (int e = 0; e < Ec; e++) {
        float af = bks[e], ag = bqs[e], av = bvs[e];
#pragma unroll
        for (int c = 0; c < Cc; c++) {
            float xv = xc[c];
            af = fmaf(Wks[e * Cc + c], xv, af);
            ag = fmaf(Wqs[e * Cc + c], xv, ag);
            av = fmaf(Wvs[e * Cc + c], xv, av);
        }
        fv[e] = af; gv[e] = ag; hv[e] = av;
    }
#pragma unroll
    for (int e = 0; e < Ec; e++) d_g[(b * Ec + e) * Nn + n] = gv[e];
#pragma unroll
    for (int e2 = 0; e2 < 4; e2++) {
        ulonglong2 rf, rh;
        rf.x = pk2(fv[2 * e2], fv[2 * e2]);     rf.y = pk2(fv[2 * e2 + 1], fv[2 * e2 + 1]);
        rh.x = pk2(hv[2 * e2], hv[2 * e2]);     rh.y = pk2(hv[2 * e2 + 1], hv[2 * e2 + 1]);
        d_f2[(b * 4 + e2) * Nn + n] = rf;
        d_h2[(b * 4 + e2) * Nn + n] = rh;
    }
}

// ============================================================
// Kernel B: attention + fused output projection.
// CTA = (batch, 64-column block), 256 threads, 8 warps, 2 CTAs/SM.
// Each lane owns 2 consecutive columns (one f32x2 pair); warp spans
// all 64 columns; the 8 warps split the i-range.
//   pass1: l[j] = sum_i exp(f_i . g_j)        -> lr[j] = -log2 l[j]
//   pass2: beta[i,j] = ex2(s*log2e + lr[j])   (STG.64 per lane)
//          v[e,j] += h[e,i] * beta
//   epilogue: y = leaky(gamma*(Wo v + bo) + x)
// ============================================================
struct __align__(16) Sm {
    union {
        struct { ulonglong2 fs[4][Ti]; ulonglong2 hs[4][Ti]; } t;  // 32 KB
        float vsc[8][Ec][64];                                      // 16 KB (reduction)
    } u;
    float lred[8][64];    // warp partials for l; reused as final v[e][j]
    float lr[64];         // -log2(l[j])
    float Wos[Cc * Ec];
    float bos[Cc];
};

__global__ __launch_bounds__(256, 2) void attn_kernel(
    const float* __restrict__ x,
    const float* __restrict__ Wo, const float* __restrict__ bo,
    const float* __restrict__ gamma,
    float* __restrict__ out_y, float* __restrict__ out_beta)
{
    __shared__ Sm sm;

    const int tid  = threadIdx.x;
    const int lane = tid & 31;
    const int wp   = tid >> 5;
    const int b    = blockIdx.y;
    const int jbase = blockIdx.x * 64;
    const int j0   = jbase + lane * 2;

    // preload output-proj weights (used only in epilogue)
    for (int i = tid; i < Cc * Ec; i += 256) sm.Wos[i] = Wo[i];
    if (tid < Cc) sm.bos[tid] = bo[tid];

    // g for this lane's 2 columns, packed (j0, j0+1)
    ull gP[Ec];
    const float* gb = d_g + b * Ec * Nn;
#pragma unroll
    for (int e = 0; e < Ec; e++) {
        float2 g2 = *(const float2*)(gb + e * Nn + j0);
        gP[e] = pk2(g2.x, g2.y);
    }

    const ulonglong2* fb = d_f2 + b * 4 * Nn;
    const ulonglong2* hb = d_h2 + b * 4 * Nn;

    // ---------------- pass 1: column sums ----------------
    float ls0 = 0.f, ls1 = 0.f;
    for (int t0 = 0; t0 < Nn; t0 += Ti) {
        __syncthreads();
#pragma unroll
        for (int e2 = 0; e2 < 4; e2++)
            sm.u.t.fs[e2][tid] = fb[e2 * Nn + t0 + tid];
        __syncthreads();
#pragma unroll
        for (int k = 0; k < 8; k++) {
            const int ib = k * 32 + wp * 4;
#pragma unroll
            for (int c = 0; c < 4; c++) {
                const int i = ib + c;
                ull s01 = 0ULL;
#pragma unroll
                for (int e2 = 0; e2 < 4; e2++) {
                    ulonglong2 fv = sm.u.t.fs[e2][i];
                    s01 = fma2(fv.x, gP[2 * e2], s01);
                    s01 = fma2(fv.y, gP[2 * e2 + 1], s01);
                }
                float2 a = up2(s01);
                ls0 += ex2(a.x * L2E);
                ls1 += ex2(a.y * L2E);
            }
        }
    }
    __syncthreads();
    *(float2*)&sm.lred[wp][lane * 2] = make_float2(ls0, ls1);
    __syncthreads();
    if (tid < 64) {
        float s = 0.f;
#pragma unroll
        for (int w = 0; w < 8; w++) s += sm.lred[w][tid];
        sm.lr[tid] = -__log2f(s);
    }
    __syncthreads();
    const float lr0 = sm.lr[lane * 2 + 0];
    const float lr1 = sm.lr[lane * 2 + 1];

    // ---------------- pass 2: beta + v ----------------
    ull vP[Ec];
#pragma unroll
    for (int e = 0; e < Ec; e++) vP[e] = 0ULL;
    float* bout = out_beta + (size_t)b * Nn * Nn + j0;

    for (int t0 = 0; t0 < Nn; t0 += Ti) {
        __syncthreads();
#pragma unroll
        for (int e2 = 0; e2 < 4; e2++) {
            sm.u.t.fs[e2][tid] = fb[e2 * Nn + t0 + tid];
            sm.u.t.hs[e2][tid] = hb[e2 * Nn + t0 + tid];
        }
        __syncthreads();
#pragma unroll
        for (int k = 0; k < 8; k++) {
            const int ib = k * 32 + wp * 4;
#pragma unroll
            for (int c = 0; c < 4; c++) {
                const int i = ib + c;
                ull s01 = 0ULL;
#pragma unroll
                for (int e2 = 0; e2 < 4; e2++) {
                    ulonglong2 fv = sm.u.t.fs[e2][i];
                    s01 = fma2(fv.x, gP[2 * e2], s01);
                    s01 = fma2(fv.y, gP[2 * e2 + 1], s01);
                }
                float2 a = up2(s01);
                float b0 = ex2(fmaf(a.x, L2E, lr0));
                float b1 = ex2(fmaf(a.y, L2E, lr1));
                *(float2*)(bout + (size_t)(t0 + i) * Nn) = make_float2(b0, b1);
                ull b01 = pk2(b0, b1);
#pragma unroll
                for (int e2 = 0; e2 < 4; e2++) {
                    ulonglong2 hv = sm.u.t.hs[e2][i];
                    vP[2 * e2]     = fma2(hv.x, b01, vP[2 * e2]);
                    vP[2 * e2 + 1] = fma2(hv.y, b01, vP[2 * e2 + 1]);
                }
            }
        }
    }

    // ---------------- reduce v across warps ----------------
    __syncthreads();   // tiles no longer needed; vsc overlays them
#pragma unroll
    for (int e = 0; e < Ec; e++) {
        float2 a = up2(vP[e]);
        *(float2*)&sm.u.vsc[wp][e][lane * 2] = a;
    }
    __syncthreads();
    for (int m = tid; m < Ec * 64; m += 256) {
        const int e = m >> 6, jl = m & 63;
        float s = 0.f;
#pragma unroll
        for (int w = 0; w < 8; w++) s += sm.u.vsc[w][e][jl];
        sm.lred[e][jl] = s;   // final v[e][jl]
    }
    __syncthreads();

    // ---------------- fused output projection ----------------
    const float gm = *gamma;
    const int jl = tid & 63;
    const int ch = (tid >> 6) * 16;           // 4 groups x 16 channels
    const float* xb = x + (size_t)b * Cc * Nn + jbase + jl;
    float* yb = out_y + (size_t)b * Cc * Nn + jbase + jl;
    float ve[Ec];
#pragma unroll
    for (int e = 0; e < Ec; e++) ve[e] = sm.lred[e][jl];
#pragma unroll
    for (int cc = 0; cc < 16; cc++) {
        const int c = ch + cc;
        float o = sm.bos[c];
#pragma unroll
        for (int e = 0; e < Ec; e++) o = fmaf(sm.Wos[c * Ec + e], ve[e], o);
        float y = fmaf(gm, o, xb[(size_t)c * Nn]);
        yb[(size_t)c * Nn] = (y >= 0.f) ? y : 0.01f * y;
    }
}

extern "C" void kernel_launch(void* const* d_in, const int* in_sizes, int n_in,
                              void* d_out, int out_size)
{
    const float* x     = (const float*)d_in[0];
    const float* Wk    = (const float*)d_in[1];
    const float* bk    = (const float*)d_in[2];
    const float* Wq    = (const float*)d_in[3];
    const float* bq    = (const float*)d_in[4];
    const float* Wv    = (const float*)d_in[5];
    const float* bv    = (const float*)d_in[6];
    const float* Wo    = (const float*)d_in[7];
    const float* bo    = (const float*)d_in[8];
    const float* gamma = (const float*)d_in[9];

    float* out_y    = (float*)d_out;                 // [B,C,H,W] first
    float* out_beta = out_y + (size_t)Bc * Cc * Nn;  // then [B,N,N]

    proj_kernel<<<dim3(Nn / 128, Bc), 128>>>(x, Wk, bk, Wq, bq, Wv, bv);
    attn_kernel<<<dim3(Nn / 64, Bc), 256>>>(x, Wo, bo, gamma, out_y, out_beta);
}

// round 16
// speedup vs baseline: 1.0768x; 1.0744x over previous
#include <cuda_runtime.h>

#define Bc 4
#define Cc 64
#define Ec 8
#define Nn 4096
#define Ti 128
#define L2E 1.4426950408889634f

typedef unsigned long long ull;

// ---- static scratch (no allocations allowed) ----
__device__ __align__(16) float d_f[Bc * Ec * Nn];
__device__ __align__(16) float d_h[Bc * Ec * Nn];
__device__ __align__(16) ull   d_g2[Bc * Ec * Nn];   // pair-replicated (g,g) per j

// ---- packed f32x2 helpers (Blackwell) ----
__device__ __forceinline__ ull pk2(float a, float b) {
    ull r; asm("mov.b64 %0,{%1,%2};" : "=l"(r) : "f"(a), "f"(b)); return r;
}
__device__ __forceinline__ float2 up2(ull v) {
    float2 r; asm("mov.b64 {%0,%1},%2;" : "=f"(r.x), "=f"(r.y) : "l"(v)); return r;
}
__device__ __forceinline__ ull fma2(ull a, ull b, ull c) {
    ull d; asm("fma.rn.f32x2 %0,%1,%2,%3;" : "=l"(d) : "l"(a), "l"(b), "l"(c)); return d;
}
__device__ __forceinline__ float ex2(float x) {
    float r; asm("ex2.approx.f32 %0,%1;" : "=f"(r) : "f"(x)); return r;
}

// ============================================================
// Kernel A: projections. Writes f/h plain float, g pair-replicated.
// ============================================================
__global__ __launch_bounds__(128) void proj_kernel(
    const float* __restrict__ x,
    const float* __restrict__ Wk, const float* __restrict__ bk,
    const float* __restrict__ Wq, const float* __restrict__ bq,
    const float* __restrict__ Wv, const float* __restrict__ bv)
{
    __shared__ float Wks[Ec * Cc], Wqs[Ec * Cc], Wvs[Ec * Cc];
    __shared__ float bks[Ec], bqs[Ec], bvs[Ec];
    const int t = threadIdx.x;
    const int b = blockIdx.y;
    const int n = blockIdx.x * 128 + t;
    for (int i = t; i < Ec * Cc; i += 128) { Wks[i] = Wk[i]; Wqs[i] = Wq[i]; Wvs[i] = Wv[i]; }
    if (t < Ec) { bks[t] = bk[t]; bqs[t] = bq[t]; bvs[t] = bv[t]; }
    __syncthreads();

    float xc[Cc];
    const float* xb = x + (size_t)b * Cc * Nn + n;
#pragma unroll
    for (int c = 0; c < Cc; c++) xc[c] = xb[(size_t)c * Nn];

#pragma unroll
    for (int e = 0; e < Ec; e++) {
        float af = bks[e], ag = bqs[e], av = bvs[e];
#pragma unroll
        for (int c = 0; c < Cc; c++) {
            float xv = xc[c];
            af = fmaf(Wks[e * Cc + c], xv, af);
            ag = fmaf(Wqs[e * Cc + c], xv, ag);
            av = fmaf(Wvs[e * Cc + c], xv, av);
        }
        const int o = (b * Ec + e) * Nn + n;
        d_f[o] = af;
        d_h[o] = av;
        d_g2[o] = pk2(ag, ag);
    }
}

// ============================================================
// Kernel B: attention + fused output projection.
// CTA = (batch, 64-column block), 256 threads, 8 warps, 2 CTAs/SM.
// Thread micro-tile: 8 i (4 natural f32x2 pairs) x 2 j.
// Warp layout: 8 j-octets (lane&7) x 4 i-slots (lane>>3);
// warps: jq = wp&3 (j quadrant), ih = wp>>2 (i half).
//   pass1: l[j] = sum_i exp(f_i.g_j)       -> lr[j] = -log2 l[j]
//   pass2: beta = ex2(s*log2e + lr[j])     (streaming float2 stores)
//          v[e,j] += h[e,i] * beta         (f32x2, halves summed at end)
//   epilogue: y = leaky(gamma*(Wo v + bo) + x)
// ============================================================
struct __align__(16) Sm {
    ull fs[Ec][Ti / 2];        // 4 KB  [e][i-pair]
    ull hs[Ec][Ti / 2];        // 4 KB
    float vpart[8][Ec][64];    // 16 KB [islot][e][j]
    float lpart[8][64];        // 2 KB
    float lr[64];
    float vfin[Ec][64];        // 2 KB
    float Wos[Cc * Ec];
    float bos[Cc];
};

__global__ __launch_bounds__(256, 2) void attn_kernel(
    const float* __restrict__ x,
    const float* __restrict__ Wo, const float* __restrict__ bo,
    const float* __restrict__ gamma,
    float* __restrict__ out_y, float* __restrict__ out_beta)
{
    __shared__ Sm sm;

    const int tid  = threadIdx.x;
    const int lane = tid & 31;
    const int wp   = tid >> 5;
    const int b    = blockIdx.y;
    const int jbase = blockIdx.x * 64;

    const int jq    = wp & 3;
    const int ih    = wp >> 2;
    const int islot = ih * 4 + (lane >> 3);        // 0..7
    const int jl    = jq * 16 + (lane & 7) * 2;    // 0..62 (even)
    const int j0    = jbase + jl;

    for (int i = tid; i < Cc * Ec; i += 256) sm.Wos[i] = Wo[i];
    if (tid < Cc) sm.bos[tid] = bo[tid];

    // g for this thread's 2 columns: persistent replicated pairs
    ull gr0[Ec], gr1[Ec];
    const ull* g2b = d_g2 + b * Ec * Nn;
#pragma unroll
    for (int e = 0; e < Ec; e++) {
        ulonglong2 gg = *(const ulonglong2*)(g2b + e * Nn + j0);
        gr0[e] = gg.x; gr1[e] = gg.y;
    }

    const float* fb = d_f + b * Ec * Nn;
    const float* hb = d_h + b * Ec * Nn;
    const int se = tid >> 5, sq = tid & 31;   // staging: warp -> e row, lane -> float4 col

    // ---------------- pass 1: column sums ----------------
    float lA = 0.f, lB = 0.f;
    for (int t0 = 0; t0 < Nn; t0 += Ti) {
        __syncthreads();
        ((float4*)sm.fs)[tid] = ((const float4*)(fb + se * Nn + t0))[sq];
        __syncthreads();
#pragma unroll
        for (int sub = 0; sub < 2; sub++) {
            const int ipb = sub * 32 + islot * 4;
            ull sA[4] = {0,0,0,0}, sB[4] = {0,0,0,0};
#pragma unroll
            for (int e = 0; e < Ec; e++) {
                ulonglong2 f01 = *(const ulonglong2*)&sm.fs[e][ipb];
                ulonglong2 f23 = *(const ulonglong2*)&sm.fs[e][ipb + 2];
                sA[0] = fma2(f01.x, gr0[e], sA[0]); sB[0] = fma2(f01.x, gr1[e], sB[0]);
                sA[1] = fma2(f01.y, gr0[e], sA[1]); sB[1] = fma2(f01.y, gr1[e], sB[1]);
                sA[2] = fma2(f23.x, gr0[e], sA[2]); sB[2] = fma2(f23.x, gr1[e], sB[2]);
                sA[3] = fma2(f23.y, gr0[e], sA[3]); sB[3] = fma2(f23.y, gr1[e], sB[3]);
            }
#pragma unroll
            for (int ip = 0; ip < 4; ip++) {
                float2 a = up2(sA[ip]); lA += ex2(a.x * L2E); lA += ex2(a.y * L2E);
                float2 c = up2(sB[ip]); lB += ex2(c.x * L2E); lB += ex2(c.y * L2E);
            }
        }
    }
    __syncthreads();
    sm.lpart[islot][jl] = lA; sm.lpart[islot][jl + 1] = lB;
    __syncthreads();
    if (tid < 64) {
        float s = 0.f;
#pragma unroll
        for (int w = 0; w < 8; w++) s += sm.lpart[w][tid];
        sm.lr[tid] = -__log2f(s);
    }
    __syncthreads();
    const float lrA = sm.lr[jl], lrB = sm.lr[jl + 1];

    // ---------------- pass 2: beta + v ----------------
    ull vA[Ec], vB[Ec];
#pragma unroll
    for (int e = 0; e < Ec; e++) { vA[e] = 0ULL; vB[e] = 0ULL; }
    float* bout = out_beta + (size_t)b * Nn * Nn + j0;

    for (int t0 = 0; t0 < Nn; t0 += Ti) {
        __syncthreads();
        ((float4*)sm.fs)[tid] = ((const float4*)(fb + se * Nn + t0))[sq];
        ((float4*)sm.hs)[tid] = ((const float4*)(hb + se * Nn + t0))[sq];
        __syncthreads();
#pragma unroll
        for (int sub = 0; sub < 2; sub++) {
            const int ipb = sub * 32 + islot * 4;
            ull sA[4] = {0,0,0,0}, sB[4] = {0,0,0,0};
#pragma unroll
            for (int e = 0; e < Ec; e++) {
                ulonglong2 f01 = *(const ulonglong2*)&sm.fs[e][ipb];
                ulonglong2 f23 = *(const ulonglong2*)&sm.fs[e][ipb + 2];
                sA[0] = fma2(f01.x, gr0[e], sA[0]); sB[0] = fma2(f01.x, gr1[e], sB[0]);
                sA[1] = fma2(f01.y, gr0[e], sA[1]); sB[1] = fma2(f01.y, gr1[e], sB[1]);
                sA[2] = fma2(f23.x, gr0[e], sA[2]); sB[2] = fma2(f23.x, gr1[e], sB[2]);
                sA[3] = fma2(f23.y, gr0[e], sA[3]); sB[3] = fma2(f23.y, gr1[e], sB[3]);
            }
            ull pA[4], pB[4];
#pragma unroll
            for (int ip = 0; ip < 4; ip++) {
                float2 a = up2(sA[ip]);
                pA[ip] = pk2(ex2(fmaf(a.x, L2E, lrA)), ex2(fmaf(a.y, L2E, lrA)));
                float2 c = up2(sB[ip]);
                pB[ip] = pk2(ex2(fmaf(c.x, L2E, lrB)), ex2(fmaf(c.y, L2E, lrB)));
            }
            const int ibase = t0 + sub * 64 + islot * 8;
#pragma unroll
            for (int ip = 0; ip < 4; ip++) {
                float2 a = up2(pA[ip]);
                float2 c = up2(pB[ip]);
                __stcs((float2*)(bout + (size_t)(ibase + 2 * ip) * Nn),     make_float2(a.x, c.x));
                __stcs((float2*)(bout + (size_t)(ibase + 2 * ip + 1) * Nn), make_float2(a.y, c.y));
            }
#pragma unroll
            for (int e = 0; e < Ec; e++) {
                ulonglong2 h01 = *(const ulonglong2*)&sm.hs[e][ipb];
                ulonglong2 h23 = *(const ulonglong2*)&sm.hs[e][ipb + 2];
                vA[e] = fma2(h01.x, pA[0], vA[e]); vB[e] = fma2(h01.x, pB[0], vB[e]);
                vA[e] = fma2(h01.y, pA[1], vA[e]); vB[e] = fma2(h01.y, pB[1], vB[e]);
                vA[e] = fma2(h23.x, pA[2], vA[e]); vB[e] = fma2(h23.x, pB[2], vB[e]);
                vA[e] = fma2(h23.y, pA[3], vA[e]); vB[e] = fma2(h23.y, pB[3], vB[e]);
            }
        }
    }

    // ---------------- reduce v across i-slots ----------------
    __syncthreads();
#pragma unroll
    for (int e = 0; e < Ec; e++) {
        float2 a = up2(vA[e]); sm.vpart[islot][e][jl]     = a.x + a.y;
        float2 c = up2(vB[e]); sm.vpart[islot][e][jl + 1] = c.x + c.y;
    }
    __syncthreads();
    for (int m = tid; m < Ec * 64; m += 256) {
        const int e = m >> 6, j = m & 63;
        float s = 0.f;
#pragma unroll
        for (int w = 0; w < 8; w++) s += sm.vpart[w][e][j];
        sm.vfin[e][j] = s;
    }
    __syncthreads();

    // ---------------- fused output projection ----------------
    const float gm = *gamma;
    const int jj = tid & 63;
    const int ch = (tid >> 6) * 16;           // 4 groups x 16 channels
    const float* xb = x + (size_t)b * Cc * Nn + jbase + jj;
    float* yb = out_y + (size_t)b * Cc * Nn + jbase + jj;
    float ve[Ec];
#pragma unroll
    for (int e = 0; e < Ec; e++) ve[e] = sm.vfin[e][jj];
#pragma unroll
    for (int cc = 0; cc < 16; cc++) {
        const int c = ch + cc;
        float o = sm.bos[c];
#pragma unroll
        for (int e = 0; e < Ec; e++) o = fmaf(sm.Wos[c * Ec + e], ve[e], o);
        float y = fmaf(gm, o, xb[(size_t)c * Nn]);
        yb[(size_t)c * Nn] = (y >= 0.f) ? y : 0.01f * y;
    }
}

extern "C" void kernel_launch(void* const* d_in, const int* in_sizes, int n_in,
                              void* d_out, int out_size)
{
    const float* x     = (const float*)d_in[0];
    const float* Wk    = (const float*)d_in[1];
    const float* bk    = (const float*)d_in[2];
    const float* Wq    = (const float*)d_in[3];
    const float* bq    = (const float*)d_in[4];
    const float* Wv    = (const float*)d_in[5];
    const float* bv    = (const float*)d_in[6];
    const float* Wo    = (const float*)d_in[7];
    const float* bo    = (const float*)d_in[8];
    const float* gamma = (const float*)d_in[9];

    float* out_y    = (float*)d_out;                 // [B,C,H,W] first
    float* out_beta = out_y + (size_t)Bc * Cc * Nn;  // then [B,N,N]

    proj_kernel<<<dim3(Nn / 128, Bc), 128>>>(x, Wk, bk, Wq, bq, Wv, bv);
    attn_kernel<<<dim3(Nn / 64, Bc), 256>>>(x, Wo, bo, gamma, out_y, out_beta);
}

// round 17
// speedup vs baseline: 1.1224x; 1.0423x over previous
#include <cuda_runtime.h>

#define Bc 4
#define Cc 64
#define Ec 8
#define Nn 4096
#define Ti 128
#define L2E 1.4426950408889634f

typedef unsigned long long ull;

// ---- static scratch (no allocations allowed) ----
__device__ __align__(16) float d_f[Bc * Ec * Nn];
__device__ __align__(16) float d_h[Bc * Ec * Nn];
__device__ __align__(16) ull   d_g2[Bc * Ec * Nn];   // pair-replicated (g,g) per j

// ---- packed f32x2 helpers (Blackwell) ----
__device__ __forceinline__ ull pk2(float a, float b) {
    ull r; asm("mov.b64 %0,{%1,%2};" : "=l"(r) : "f"(a), "f"(b)); return r;
}
__device__ __forceinline__ float2 up2(ull v) {
    float2 r; asm("mov.b64 {%0,%1},%2;" : "=f"(r.x), "=f"(r.y) : "l"(v)); return r;
}
__device__ __forceinline__ ull fma2(ull a, ull b, ull c) {
    ull d; asm("fma.rn.f32x2 %0,%1,%2,%3;" : "=l"(d) : "l"(a), "l"(b), "l"(c)); return d;
}
__device__ __forceinline__ float ex2(float x) {
    float r; asm("ex2.approx.f32 %0,%1;" : "=f"(r) : "f"(x)); return r;
}

// ============================================================
// Kernel A: projections. Writes f/h plain float, g pair-replicated.
// ============================================================
__global__ __launch_bounds__(128) void proj_kernel(
    const float* __restrict__ x,
    const float* __restrict__ Wk, const float* __restrict__ bk,
    const float* __restrict__ Wq, const float* __restrict__ bq,
    const float* __restrict__ Wv, const float* __restrict__ bv)
{
    __shared__ float Wks[Ec * Cc], Wqs[Ec * Cc], Wvs[Ec * Cc];
    __shared__ float bks[Ec], bqs[Ec], bvs[Ec];
    const int t = threadIdx.x;
    const int b = blockIdx.y;
    const int n = blockIdx.x * 128 + t;
    for (int i = t; i < Ec * Cc; i += 128) { Wks[i] = Wk[i]; Wqs[i] = Wq[i]; Wvs[i] = Wv[i]; }
    if (t < Ec) { bks[t] = bk[t]; bqs[t] = bq[t]; bvs[t] = bv[t]; }
    __syncthreads();

    float xc[Cc];
    const float* xb = x + (size_t)b * Cc * Nn + n;
#pragma unroll
    for (int c = 0; c < Cc; c++) xc[c] = xb[(size_t)c * Nn];

#pragma unroll
    for (int e = 0; e < Ec; e++) {
        float af = bks[e], ag = bqs[e], av = bvs[e];
#pragma unroll
        for (int c = 0; c < Cc; c++) {
            float xv = xc[c];
            af = fmaf(Wks[e * Cc + c], xv, af);
            ag = fmaf(Wqs[e * Cc + c], xv, ag);
            av = fmaf(Wvs[e * Cc + c], xv, av);
        }
        const int o = (b * Ec + e) * Nn + n;
        d_f[o] = af;
        d_h[o] = av;
        d_g2[o] = pk2(ag, ag);
    }
}

// ============================================================
// Kernel B: attention + fused output projection.
// CTA = (batch, 64-column block), 256 threads, 8 warps, 2 CTAs/SM.
// Thread micro-tile: 8 i (4 natural f32x2 pairs) x 2 j.
// Double-buffered smem tile staging: prefetch tile t+1 while
// computing tile t; ONE __syncthreads per tile.
// ============================================================
struct __align__(16) Sm {
    ull fs[2][Ec][Ti / 2];     // 8 KB  double-buffered [buf][e][i-pair]
    ull hs[2][Ec][Ti / 2];     // 8 KB
    float vpart[8][Ec][64];    // 16 KB [islot][e][j]
    float lpart[8][64];        // 2 KB
    float lr[64];
    float vfin[Ec][64];        // 2 KB
    float Wos[Cc * Ec];
    float bos[Cc];
};

__global__ __launch_bounds__(256, 2) void attn_kernel(
    const float* __restrict__ x,
    const float* __restrict__ Wo, const float* __restrict__ bo,
    const float* __restrict__ gamma,
    float* __restrict__ out_y, float* __restrict__ out_beta)
{
    __shared__ Sm sm;

    const int tid  = threadIdx.x;
    const int lane = tid & 31;
    const int wp   = tid >> 5;
    const int b    = blockIdx.y;
    const int jbase = blockIdx.x * 64;

    const int jq    = wp & 3;
    const int ih    = wp >> 2;
    const int islot = ih * 4 + (lane >> 3);        // 0..7
    const int jl    = jq * 16 + (lane & 7) * 2;    // 0..62 (even)
    const int j0    = jbase + jl;

    for (int i = tid; i < Cc * Ec; i += 256) sm.Wos[i] = Wo[i];
    if (tid < Cc) sm.bos[tid] = bo[tid];

    // g for this thread's 2 columns: persistent replicated pairs
    ull gr0[Ec], gr1[Ec];
    const ull* g2b = d_g2 + b * Ec * Nn;
#pragma unroll
    for (int e = 0; e < Ec; e++) {
        ulonglong2 gg = *(const ulonglong2*)(g2b + e * Nn + j0);
        gr0[e] = gg.x; gr1[e] = gg.y;
    }

    const int se = tid >> 5, sq = tid & 31;   // staging: warp -> e row, lane -> float4 col
    const float4* fsrc = (const float4*)(d_f + b * Ec * Nn + se * Nn) + sq;
    const float4* hsrc = (const float4*)(d_h + b * Ec * Nn + se * Nn) + sq;

    // ---------------- pass 1: column sums ----------------
    float lA = 0.f, lB = 0.f;
    {
        float4 pf = fsrc[0];
        int p = 0;
        for (int t0 = 0; t0 < Nn; t0 += Ti) {
            ((float4*)sm.fs[p])[tid] = pf;
            __syncthreads();
            if (t0 + Ti < Nn) pf = fsrc[(t0 + Ti) >> 2];
#pragma unroll
            for (int sub = 0; sub < 2; sub++) {
                const int ipb = sub * 32 + islot * 4;
                ull sA[4] = {0,0,0,0}, sB[4] = {0,0,0,0};
#pragma unroll
                for (int e = 0; e < Ec; e++) {
                    ulonglong2 f01 = *(const ulonglong2*)&sm.fs[p][e][ipb];
                    ulonglong2 f23 = *(const ulonglong2*)&sm.fs[p][e][ipb + 2];
                    sA[0] = fma2(f01.x, gr0[e], sA[0]); sB[0] = fma2(f01.x, gr1[e], sB[0]);
                    sA[1] = fma2(f01.y, gr0[e], sA[1]); sB[1] = fma2(f01.y, gr1[e], sB[1]);
                    sA[2] = fma2(f23.x, gr0[e], sA[2]); sB[2] = fma2(f23.x, gr1[e], sB[2]);
                    sA[3] = fma2(f23.y, gr0[e], sA[3]); sB[3] = fma2(f23.y, gr1[e], sB[3]);
                }
#pragma unroll
                for (int ip = 0; ip < 4; ip++) {
                    float2 a = up2(sA[ip]); lA += ex2(a.x * L2E); lA += ex2(a.y * L2E);
                    float2 c = up2(sB[ip]); lB += ex2(c.x * L2E); lB += ex2(c.y * L2E);
                }
            }
            p ^= 1;
        }
    }
    __syncthreads();
    sm.lpart[islot][jl] = lA; sm.lpart[islot][jl + 1] = lB;
    __syncthreads();
    if (tid < 64) {
        float s = 0.f;
#pragma unroll
        for (int w = 0; w < 8; w++) s += sm.lpart[w][tid];
        sm.lr[tid] = -__log2f(s);
    }
    __syncthreads();
    const float lrA = sm.lr[jl], lrB = sm.lr[jl + 1];

    // ---------------- pass 2: beta + v ----------------
    ull vA[Ec], vB[Ec];
#pragma unroll
    for (int e = 0; e < Ec; e++) { vA[e] = 0ULL; vB[e] = 0ULL; }

    // running row pointer: rows (t0 + sub*64 + islot*8 + r), columns (j0, j0+1)
    float* brow = out_beta + (size_t)b * Nn * Nn + (size_t)(islot * 8) * Nn + j0;

    {
        float4 pf = fsrc[0];
        float4 ph = hsrc[0];
        int p = 0;
        for (int t0 = 0; t0 < Nn; t0 += Ti) {
            ((float4*)sm.fs[p])[tid] = pf;
            ((float4*)sm.hs[p])[tid] = ph;
            __syncthreads();
            if (t0 + Ti < Nn) {
                pf = fsrc[(t0 + Ti) >> 2];
                ph = hsrc[(t0 + Ti) >> 2];
            }
#pragma unroll
            for (int sub = 0; sub < 2; sub++) {
                const int ipb = sub * 32 + islot * 4;
                ull sA[4] = {0,0,0,0}, sB[4] = {0,0,0,0};
#pragma unroll
                for (int e = 0; e < Ec; e++) {
                    ulonglong2 f01 = *(const ulonglong2*)&sm.fs[p][e][ipb];
                    ulonglong2 f23 = *(const ulonglong2*)&sm.fs[p][e][ipb + 2];
                    sA[0] = fma2(f01.x, gr0[e], sA[0]); sB[0] = fma2(f01.x, gr1[e], sB[0]);
                    sA[1] = fma2(f01.y, gr0[e], sA[1]); sB[1] = fma2(f01.y, gr1[e], sB[1]);
                    sA[2] = fma2(f23.x, gr0[e], sA[2]); sB[2] = fma2(f23.x, gr1[e], sB[2]);
                    sA[3] = fma2(f23.y, gr0[e], sA[3]); sB[3] = fma2(f23.y, gr1[e], sB[3]);
                }
                float* bp = brow + (size_t)(sub * 64) * Nn;
                ull pA[4], pB[4];
#pragma unroll
                for (int ip = 0; ip < 4; ip++) {
                    float2 a = up2(sA[ip]);
                    float eA0 = ex2(fmaf(a.x, L2E, lrA));
                    float eA1 = ex2(fmaf(a.y, L2E, lrA));
                    float2 c = up2(sB[ip]);
                    float eB0 = ex2(fmaf(c.x, L2E, lrB));
                    float eB1 = ex2(fmaf(c.y, L2E, lrB));
                    __stcs((float2*)(bp + (size_t)(2 * ip) * Nn),     make_float2(eA0, eB0));
                    __stcs((float2*)(bp + (size_t)(2 * ip + 1) * Nn), make_float2(eA1, eB1));
                    pA[ip] = pk2(eA0, eA1);
                    pB[ip] = pk2(eB0, eB1);
                }
#pragma unroll
                for (int e = 0; e < Ec; e++) {
                    ulonglong2 h01 = *(const ulonglong2*)&sm.hs[p][e][ipb];
                    ulonglong2 h23 = *(const ulonglong2*)&sm.hs[p][e][ipb + 2];
                    vA[e] = fma2(h01.x, pA[0], vA[e]); vB[e] = fma2(h01.x, pB[0], vB[e]);
                    vA[e] = fma2(h01.y, pA[1], vA[e]); vB[e] = fma2(h01.y, pB[1], vB[e]);
                    vA[e] = fma2(h23.x, pA[2], vA[e]); vB[e] = fma2(h23.x, pB[2], vB[e]);
                    vA[e] = fma2(h23.y, pA[3], vA[e]); vB[e] = fma2(h23.y, pB[3], vB[e]);
                }
            }
            brow += (size_t)Ti * Nn;
            p ^= 1;
        }
    }

    // ---------------- reduce v across i-slots ----------------
    __syncthreads();
#pragma unroll
    for (int e = 0; e < Ec; e++) {
        float2 a = up2(vA[e]); sm.vpart[islot][e][jl]     = a.x + a.y;
        float2 c = up2(vB[e]); sm.vpart[islot][e][jl + 1] = c.x + c.y;
    }
    __syncthreads();
    for (int m = tid; m < Ec * 64; m += 256) {
        const int e = m >> 6, j = m & 63;
        float s = 0.f;
#pragma unroll
        for (int w = 0; w < 8; w++) s += sm.vpart[w][e][j];
        sm.vfin[e][j] = s;
    }
    __syncthreads();

    // ---------------- fused output projection ----------------
    const float gm = *gamma;
    const int jj = tid & 63;
    const int ch = (tid >> 6) * 16;           // 4 groups x 16 channels
    const float* xb = x + (size_t)b * Cc * Nn + jbase + jj;
    float* yb = out_y + (size_t)b * Cc * Nn + jbase + jj;
    float ve[Ec];
#pragma unroll
    for (int e = 0; e < Ec; e++) ve[e] = sm.vfin[e][jj];
#pragma unroll
    for (int cc = 0; cc < 16; cc++) {
        const int c = ch + cc;
        float o = sm.bos[c];
#pragma unroll
        for (int e = 0; e < Ec; e++) o = fmaf(sm.Wos[c * Ec + e], ve[e], o);
        float y = fmaf(gm, o, xb[(size_t)c * Nn]);
        yb[(size_t)c * Nn] = (y >= 0.f) ? y : 0.01f * y;
    }
}

extern "C" void kernel_launch(void* const* d_in, const int* in_sizes, int n_in,
                              void* d_out, int out_size)
{
    const float* x     = (const float*)d_in[0];
    const float* Wk    = (const float*)d_in[1];
    const float* bk    = (const float*)d_in[2];
    const float* Wq    = (const float*)d_in[3];
    const float* bq    = (const float*)d_in[4];
    const float* Wv    = (const float*)d_in[5];
    const float* bv    = (const float*)d_in[6];
    const float* Wo    = (const float*)d_in[7];
    const float* bo    = (const float*)d_in[8];
    const float* gamma = (const float*)d_in[9];

    float* out_y    = (float*)d_out;                 // [B,C,H,W] first
    float* out_beta = out_y + (size_t)Bc * Cc * Nn;  // then [B,N,N]

    proj_kernel<<<dim3(Nn / 128, Bc), 128>>>(x, Wk, bk, Wq, bq, Wv, bv);
    attn_kernel<<<dim3(Nn / 64, Bc), 256>>>(x, Wo, bo, gamma, out_y, out_beta);
}